// round 16
// baseline (speedup 1.0000x reference)
#include <cuda_runtime.h>
#include <cuda_bf16.h>
#include <cstdint>

// OptionAttentionSum: out[b,o] = (sum_w sum_l [doc[b,l]==opt[b,o,w]] * prob[b,l]) / #nonzero words
//
// R9 = R8 (128 CTAs x 1024 thr, 2048-slot table, entry prefetch) + tail/head cuts:
//  - inserters REMEMBER their resolved slot -> epilogue needs zero hash probes:
//    50 threads do one parallel LDS each (s_val[tid] = s_acc[my_slot]), barrier,
//    10 threads sum 5 independent LDS + divide + store.  Dependent-chain tail
//    ~400cyc -> ~100cyc.
//  - table init via one STS.64 per thread (int2 of KEMPTY) instead of 2x STS.32.
// Kernel is latency-bound ~1.2us above the ~4.9us floor; only serialized-phase
// length matters now.

static constexpr int B = 128;
static constexpr int L = 4096;
static constexpr int O = 10;
static constexpr int W = 5;
static constexpr int OW = O * W;          // 50
static constexpr int THREADS = 1024;      // L/4 -> one int4 per thread
static constexpr int TSIZE = 2048;        // hash slots (power of 2), load ~0.024
static constexpr int KEMPTY = (int)0x80000000;  // impossible key (values in [0, 50000))

__device__ __forceinline__ unsigned hash_key(int key) {
    return ((unsigned)key * 2654435761u) >> (32 - 11);   // top 11 bits -> [0,2048)
}

__global__ __launch_bounds__(THREADS, 1)
void oas_kernel(const int* __restrict__ doc_idx,
                const float* __restrict__ doc_prob,
                const int* __restrict__ options,
                float* __restrict__ out) {
    __shared__ int   s_key[TSIZE];
    __shared__ float s_acc[TSIZE];
    __shared__ int   s_opt[OW];     // option keys (for nonzero count)
    __shared__ float s_val[OW];     // per-(o,w) looked-up sums

    const int b   = blockIdx.x;
    const int tid = threadIdx.x;

    // ---- issue ALL global loads first: doc (2x LDG.128) + options (tid<50) ----
    const int4   d4 = reinterpret_cast<const int4*>(doc_idx  + b * L)[tid];
    const float4 p4 = reinterpret_cast<const float4*>(doc_prob + b * L)[tid];

    int my_key = 0;
    if (tid < OW) my_key = options[b * OW + tid];   // latency overlaps init below

    // ---- init keys: one STS.64 per thread ----
    reinterpret_cast<int2*>(s_key)[tid] = make_int2(KEMPTY, KEMPTY);
    __syncthreads();

    // ---- insert the (<=50) option words; remember the resolved slot ----
    unsigned my_slot = 0;
    if (tid < OW) {
        s_opt[tid] = my_key;
        unsigned h = hash_key(my_key);
        while (true) {
            int old = atomicCAS(&s_key[h], KEMPTY, my_key);
            if (old == KEMPTY || old == my_key) break;   // dup keys converge to one slot
            h = (h + 1) & (TSIZE - 1);
        }
        my_slot = h;
        s_acc[h] = 0.0f;            // zero only occupied slots (dups: same slot, same 0)
    }
    __syncthreads();

    // ---- probe: 4 independent first-probe LDS before any branching ----
    const int   dk[4] = {d4.x, d4.y, d4.z, d4.w};
    const float pp[4] = {p4.x, p4.y, p4.z, p4.w};

    unsigned hh[4];
    int      k0[4];
    #pragma unroll
    for (int j = 0; j < 4; j++) hh[j] = hash_key(dk[j]);
    #pragma unroll
    for (int j = 0; j < 4; j++) k0[j] = s_key[hh[j]];

    #pragma unroll
    for (int j = 0; j < 4; j++) {
        if (k0[j] == dk[j]) {
            atomicAdd(&s_acc[hh[j]], pp[j]);      // hit on first probe
        } else if (k0[j] != KEMPTY) {             // rare: collided slot, walk the cluster
            unsigned h = (hh[j] + 1) & (TSIZE - 1);
            while (true) {
                const int k = s_key[h];
                if (k == KEMPTY) break;
                if (k == dk[j]) { atomicAdd(&s_acc[h], pp[j]); break; }
                h = (h + 1) & (TSIZE - 1);
            }
        }
        // first slot EMPTY (~96%): miss, fall through
    }
    __syncthreads();

    // ---- epilogue stage 1: 50 parallel single-LDS lookups (no probing) ----
    if (tid < OW) {
        s_val[tid] = s_acc[my_slot];
    }
    __syncthreads();

    // ---- epilogue stage 2: 10 threads, 5 independent LDS each + divide ----
    if (tid < O) {
        float sum = 0.0f;
        float cnt = 0.0f;
        #pragma unroll
        for (int w = 0; w < W; w++) {
            sum += s_val[tid * W + w];
            if (s_opt[tid * W + w] != 0) cnt += 1.0f;
        }
        out[b * O + tid] = sum / cnt;
    }
}

extern "C" void kernel_launch(void* const* d_in, const int* in_sizes, int n_in,
                              void* d_out, int out_size) {
    const int*   doc_idx  = (const int*)d_in[0];     // (B, L) int32 (JAX-downgraded int64)
    const float* doc_prob = (const float*)d_in[1];   // (B, L) float32
    const int*   options  = (const int*)d_in[2];     // (B, O, W) int32
    float*       out      = (float*)d_out;           // (B, O) float32

    oas_kernel<<<B, THREADS>>>(doc_idx, doc_prob, options, out);
}